// round 12
// baseline (speedup 1.0000x reference)
#include <cuda_runtime.h>
#include <cstdint>

#define NMAX 50000
#define EMAX 1600000
#define HD   128

// ---------------- device scratch (static allocation, no cudaMalloc) ----------
__device__ int   g_deg[NMAX];
__device__ float g_dinv[NMAX];
__device__ int   g_rowptr[NMAX + 1];
__device__ int   g_fill[NMAX];
__device__ int   g_col[EMAX];
__device__ int   g_bsum[64];
__device__ float g_hs[(size_t)NMAX * HD];   // h = A @ W (gather source)
__device__ float g_h [(size_t)NMAX * HD];   // layer-1 output

// ---------------- degree ----------------------------------------------------
__global__ void k_deg_zero(int n) {
    int i = blockIdx.x * blockDim.x + threadIdx.x;
    if (i < n) g_deg[i] = 0;
}
__global__ void k_deg_count(const int* __restrict__ dst, int e, int n) {
    int i = blockIdx.x * blockDim.x + threadIdx.x;
    if (i < e) {
        int d = dst[i];
        if ((unsigned)d < (unsigned)n) atomicAdd(&g_deg[d], 1);
    }
}

// ---------------- parallel exclusive scan of deg ----------------------------
__global__ __launch_bounds__(1024) void k_scan1(int n) {
    __shared__ int ss[1024];
    int tid = threadIdx.x;
    int i = blockIdx.x * 1024 + tid;
    int v = (i < n) ? g_deg[i] : 0;
    if (i < n) g_dinv[i] = rsqrtf((float)(v + 1));
    ss[tid] = v;
    __syncthreads();
#pragma unroll
    for (int off = 1; off < 1024; off <<= 1) {
        int t = (tid >= off) ? ss[tid - off] : 0;
        __syncthreads();
        ss[tid] += t;
        __syncthreads();
    }
    if (i < n) g_rowptr[i] = ss[tid] - v;
    if (tid == 1023) g_bsum[blockIdx.x] = ss[1023];
}
__global__ __launch_bounds__(1024) void k_scan3(int n) {
    __shared__ int off_s;
    if (threadIdx.x == 0) {
        int o = 0;
        for (int j = 0; j < (int)blockIdx.x; j++) o += g_bsum[j];
        off_s = o;
    }
    __syncthreads();
    int i = blockIdx.x * 1024 + threadIdx.x;
    if (i >= n) return;
    int rp = g_rowptr[i] + off_s;
    g_rowptr[i] = rp;
    g_fill[i] = rp;
    if (i == n - 1) g_rowptr[n] = rp + g_deg[i];
}
__global__ void k_fill(const int* __restrict__ src,
                       const int* __restrict__ dst, int e, int n) {
    int i = blockIdx.x * blockDim.x + threadIdx.x;
    if (i >= e) return;
    int d = dst[i];
    int s = src[i];
    if ((unsigned)d >= (unsigned)n || (unsigned)s >= (unsigned)n) return;
    int pos = atomicAdd(&g_fill[d], 1);
    if (pos < EMAX) g_col[pos] = s;
}

// ---------------- GEMM: g_hs = A @ W  (rows [roff, roff+128*grid) ) ----------
// 128x128 block tile, 256 threads, 8x8 register tile, fma.rn.f32x2 (FFMA2).
// Per-element k-accumulation order: sequential 0..127 (bit-identical to R8).
template <int SRC>
__global__ __launch_bounds__(256) void k_gemm(const float* __restrict__ Ax,
                                              const float* __restrict__ W,
                                              int roff, int M) {
    const float* __restrict__ A = (SRC == 0) ? Ax : g_h;
    __shared__ float XsT[32][132];   // [k][m], padded
    __shared__ float Ws[32][128];    // [k][n]
    int tid = threadIdx.x;
    int row0 = roff + blockIdx.x * 128;
    int tr = tid >> 4;    // 0..15 -> rows tr*8..tr*8+7
    int tc = tid & 15;    // 0..15 -> cols tc*8..tc*8+7

    unsigned long long acc[8][4];    // [i][j2]: packed pair of adjacent columns
#pragma unroll
    for (int i = 0; i < 8; i++)
#pragma unroll
        for (int j = 0; j < 4; j++) acc[i][j] = 0ULL;

    for (int k0 = 0; k0 < 128; k0 += 32) {
#pragma unroll
        for (int l = 0; l < 4; l++) {
            int f = tid + l * 256;        // 0..1023
            int k4 = f >> 7;              // 0..7 (k-group of 4)
            int m = f & 127;              // row within tile
            int grow = row0 + m;
            float4 v = make_float4(0.f, 0.f, 0.f, 0.f);
            if (grow < M) v = *(const float4*)&A[(size_t)grow * 128 + k0 + (k4 << 2)];
            XsT[(k4 << 2) + 0][m] = v.x;
            XsT[(k4 << 2) + 1][m] = v.y;
            XsT[(k4 << 2) + 2][m] = v.z;
            XsT[(k4 << 2) + 3][m] = v.w;
        }
#pragma unroll
        for (int l = 0; l < 4; l++) {
            int f = tid + l * 256;        // 0..1023
            int r = f >> 5;
            int c = (f & 31) << 2;
            *(float4*)&Ws[r][c] = *(const float4*)&W[(size_t)(k0 + r) * 128 + c];
        }
        __syncthreads();
#pragma unroll
        for (int kk = 0; kk < 32; kk++) {
            float a8[8];
            *(float4*)&a8[0] = *(const float4*)&XsT[kk][tr * 8];
            *(float4*)&a8[4] = *(const float4*)&XsT[kk][tr * 8 + 4];
            ulonglong2 t0 = *(const ulonglong2*)&Ws[kk][tc * 8];
            ulonglong2 t1 = *(const ulonglong2*)&Ws[kk][tc * 8 + 4];
            unsigned long long b4[4] = {t0.x, t0.y, t1.x, t1.y};
#pragma unroll
            for (int i = 0; i < 8; i++) {
                unsigned long long aa;
                unsigned int ai = __float_as_uint(a8[i]);
                asm("mov.b64 %0, {%1, %1};" : "=l"(aa) : "r"(ai));
#pragma unroll
                for (int j = 0; j < 4; j++)
                    asm("fma.rn.f32x2 %0, %1, %2, %3;"
                        : "=l"(acc[i][j])
                        : "l"(aa), "l"(b4[j]), "l"(acc[i][j]));
            }
        }
        __syncthreads();
    }
#pragma unroll
    for (int i = 0; i < 8; i++) {
        int row = row0 + tr * 8 + i;
        if (row < M) {
            *(ulonglong2*)&g_hs[(size_t)row * 128 + tc * 8] =
                make_ulonglong2(acc[i][0], acc[i][1]);
            *(ulonglong2*)&g_hs[(size_t)row * 128 + tc * 8 + 4] =
                make_ulonglong2(acc[i][2], acc[i][3]);
        }
    }
}

// ---------------- aggregation: one warp per node in [n0,n1), CSR gather -----
__global__ __launch_bounds__(256) void k_agg(const float* __restrict__ bias,
                                             int n0, int n1) {
    int node = n0 + (int)((blockIdx.x * blockDim.x + threadIdx.x) >> 5);
    int lane = threadIdx.x & 31;
    if (node >= n1) return;
    const float4* __restrict__ hs4 = (const float4*)g_hs;
    float dn = g_dinv[node];
    float4 hv = hs4[(size_t)node * 32 + lane];
    float4 acc;
    acc.x = __fmul_rn(hv.x, dn);
    acc.y = __fmul_rn(hv.y, dn);
    acc.z = __fmul_rn(hv.z, dn);
    acc.w = __fmul_rn(hv.w, dn);
    int beg = __ldg(&g_rowptr[node]);
    int end = __ldg(&g_rowptr[node + 1]);
    int e = beg;
    for (; e + 8 <= end; e += 8) {
        int   s[8];
        float d[8];
        float4 v[8];
#pragma unroll
        for (int u = 0; u < 8; u++) s[u] = __ldg(&g_col[e + u]);
#pragma unroll
        for (int u = 0; u < 8; u++) d[u] = __ldg(&g_dinv[s[u]]);
#pragma unroll
        for (int u = 0; u < 8; u++) v[u] = __ldg(&hs4[(size_t)s[u] * 32 + lane]);
        float4 p0, p1;
        p0.x = (__fmul_rn(v[0].x, d[0]) + __fmul_rn(v[1].x, d[1])) + (__fmul_rn(v[2].x, d[2]) + __fmul_rn(v[3].x, d[3]));
        p0.y = (__fmul_rn(v[0].y, d[0]) + __fmul_rn(v[1].y, d[1])) + (__fmul_rn(v[2].y, d[2]) + __fmul_rn(v[3].y, d[3]));
        p0.z = (__fmul_rn(v[0].z, d[0]) + __fmul_rn(v[1].z, d[1])) + (__fmul_rn(v[2].z, d[2]) + __fmul_rn(v[3].z, d[3]));
        p0.w = (__fmul_rn(v[0].w, d[0]) + __fmul_rn(v[1].w, d[1])) + (__fmul_rn(v[2].w, d[2]) + __fmul_rn(v[3].w, d[3]));
        p1.x = (__fmul_rn(v[4].x, d[4]) + __fmul_rn(v[5].x, d[5])) + (__fmul_rn(v[6].x, d[6]) + __fmul_rn(v[7].x, d[7]));
        p1.y = (__fmul_rn(v[4].y, d[4]) + __fmul_rn(v[5].y, d[5])) + (__fmul_rn(v[6].y, d[6]) + __fmul_rn(v[7].y, d[7]));
        p1.z = (__fmul_rn(v[4].z, d[4]) + __fmul_rn(v[5].z, d[5])) + (__fmul_rn(v[6].z, d[6]) + __fmul_rn(v[7].z, d[7]));
        p1.w = (__fmul_rn(v[4].w, d[4]) + __fmul_rn(v[5].w, d[5])) + (__fmul_rn(v[6].w, d[6]) + __fmul_rn(v[7].w, d[7]));
        acc.x += p0.x + p1.x;
        acc.y += p0.y + p1.y;
        acc.z += p0.z + p1.z;
        acc.w += p0.w + p1.w;
    }
    for (; e < end; e++) {
        int s = __ldg(&g_col[e]);
        float ds = __ldg(&g_dinv[s]);
        float4 v = __ldg(&hs4[(size_t)s * 32 + lane]);
        acc.x += __fmul_rn(v.x, ds);
        acc.y += __fmul_rn(v.y, ds);
        acc.z += __fmul_rn(v.z, ds);
        acc.w += __fmul_rn(v.w, ds);
    }
    float4 bb = __ldg(&((const float4*)bias)[lane]);
    float4 o;
    o.x = fmaxf(fmaf(dn, acc.x, bb.x), 0.f);
    o.y = fmaxf(fmaf(dn, acc.y, bb.y), 0.f);
    o.z = fmaxf(fmaf(dn, acc.z, bb.z), 0.f);
    o.w = fmaxf(fmaf(dn, acc.w, bb.w), 0.f);
    ((float4*)g_h)[(size_t)node * 32 + lane] = o;
}

// ---------------- fused agg2 + classifier head (R10-validated) --------------
__global__ __launch_bounds__(256) void k_agg_final(const float* __restrict__ bias,
                                                   const float* __restrict__ Wc,
                                                   const float* __restrict__ bc,
                                                   float* __restrict__ Out, int n) {
    __shared__ float Wcs[128 * 16];
    __shared__ float bcs[16];
    int tid = threadIdx.x;
    for (int i = tid; i < 128 * 16; i += 256) Wcs[i] = Wc[i];
    if (tid < 16) bcs[tid] = bc[tid];
    __syncthreads();
    int node = (int)((blockIdx.x * blockDim.x + tid) >> 5);
    int lane = tid & 31;
    if (node >= n) return;
    const float4* __restrict__ hs4 = (const float4*)g_hs;
    float dn = g_dinv[node];
    float4 hv = hs4[(size_t)node * 32 + lane];
    float4 acc;
    acc.x = __fmul_rn(hv.x, dn);
    acc.y = __fmul_rn(hv.y, dn);
    acc.z = __fmul_rn(hv.z, dn);
    acc.w = __fmul_rn(hv.w, dn);
    int beg = __ldg(&g_rowptr[node]);
    int end = __ldg(&g_rowptr[node + 1]);
    int e = beg;
    for (; e + 8 <= end; e += 8) {
        int   s[8];
        float d[8];
        float4 v[8];
#pragma unroll
        for (int u = 0; u < 8; u++) s[u] = __ldg(&g_col[e + u]);
#pragma unroll
        for (int u = 0; u < 8; u++) d[u] = __ldg(&g_dinv[s[u]]);
#pragma unroll
        for (int u = 0; u < 8; u++) v[u] = __ldg(&hs4[(size_t)s[u] * 32 + lane]);
        float4 p0, p1;
        p0.x = (__fmul_rn(v[0].x, d[0]) + __fmul_rn(v[1].x, d[1])) + (__fmul_rn(v[2].x, d[2]) + __fmul_rn(v[3].x, d[3]));
        p0.y = (__fmul_rn(v[0].y, d[0]) + __fmul_rn(v[1].y, d[1])) + (__fmul_rn(v[2].y, d[2]) + __fmul_rn(v[3].y, d[3]));
        p0.z = (__fmul_rn(v[0].z, d[0]) + __fmul_rn(v[1].z, d[1])) + (__fmul_rn(v[2].z, d[2]) + __fmul_rn(v[3].z, d[3]));
        p0.w = (__fmul_rn(v[0].w, d[0]) + __fmul_rn(v[1].w, d[1])) + (__fmul_rn(v[2].w, d[2]) + __fmul_rn(v[3].w, d[3]));
        p1.x = (__fmul_rn(v[4].x, d[4]) + __fmul_rn(v[5].x, d[5])) + (__fmul_rn(v[6].x, d[6]) + __fmul_rn(v[7].x, d[7]));
        p1.y = (__fmul_rn(v[4].y, d[4]) + __fmul_rn(v[5].y, d[5])) + (__fmul_rn(v[6].y, d[6]) + __fmul_rn(v[7].y, d[7]));
        p1.z = (__fmul_rn(v[4].z, d[4]) + __fmul_rn(v[5].z, d[5])) + (__fmul_rn(v[6].z, d[6]) + __fmul_rn(v[7].z, d[7]));
        p1.w = (__fmul_rn(v[4].w, d[4]) + __fmul_rn(v[5].w, d[5])) + (__fmul_rn(v[6].w, d[6]) + __fmul_rn(v[7].w, d[7]));
        acc.x += p0.x + p1.x;
        acc.y += p0.y + p1.y;
        acc.z += p0.z + p1.z;
        acc.w += p0.w + p1.w;
    }
    for (; e < end; e++) {
        int s = __ldg(&g_col[e]);
        float ds = __ldg(&g_dinv[s]);
        float4 v = __ldg(&hs4[(size_t)s * 32 + lane]);
        acc.x += __fmul_rn(v.x, ds);
        acc.y += __fmul_rn(v.y, ds);
        acc.z += __fmul_rn(v.z, ds);
        acc.w += __fmul_rn(v.w, ds);
    }
    float4 bb = __ldg(&((const float4*)bias)[lane]);
    float h2[4];
    h2[0] = fmaxf(fmaf(dn, acc.x, bb.x), 0.f);
    h2[1] = fmaxf(fmaf(dn, acc.y, bb.y), 0.f);
    h2[2] = fmaxf(fmaf(dn, acc.z, bb.z), 0.f);
    h2[3] = fmaxf(fmaf(dn, acc.w, bb.w), 0.f);
    float p[16];
#pragma unroll
    for (int j = 0; j < 16; j++) p[j] = 0.f;
    int kbase = lane * 4;
#pragma unroll
    for (int t = 0; t < 4; t++) {
        float ht = h2[t];
        const float* wr = &Wcs[(kbase + t) * 16];
#pragma unroll
        for (int j4 = 0; j4 < 4; j4++) {
            float4 w = *(const float4*)&wr[j4 * 4];
            p[j4 * 4 + 0] += ht * w.x;
            p[j4 * 4 + 1] += ht * w.y;
            p[j4 * 4 + 2] += ht * w.z;
            p[j4 * 4 + 3] += ht * w.w;
        }
    }
#pragma unroll
    for (int off = 16; off >= 1; off >>= 1)
#pragma unroll
        for (int j = 0; j < 16; j++)
            p[j] += __shfl_xor_sync(0xffffffffu, p[j], off);
    if (lane < 4) {
        float4 ov;
        ov.x = p[lane * 4 + 0] + bcs[lane * 4 + 0];
        ov.y = p[lane * 4 + 1] + bcs[lane * 4 + 1];
        ov.z = p[lane * 4 + 2] + bcs[lane * 4 + 2];
        ov.w = p[lane * 4 + 3] + bcs[lane * 4 + 3];
        *(float4*)&Out[(size_t)node * 16 + lane * 4] = ov;
    }
}

// ---------------- launcher ---------------------------------------------------
extern "C" void kernel_launch(void* const* d_in, const int* in_sizes, int n_in,
                              void* d_out, int out_size) {
    const float* x  = (const float*)d_in[0];
    const int*   ei = (const int*)d_in[1];
    const float* W1 = (const float*)d_in[2];
    const float* b1 = (const float*)d_in[3];
    const float* W2 = (const float*)d_in[4];
    const float* b2 = (const float*)d_in[5];
    const float* Wc = (const float*)d_in[6];
    const float* bc = (const float*)d_in[7];
    float* out = (float*)d_out;

    int n = in_sizes[0] / HD;       // 50000
    int e = in_sizes[1] / 2;        // 1600000
    const int* srcp = ei;
    const int* dstp = ei + e;

    int gn256 = (n + 255) / 256;
    int ge256 = (e + 255) / 256;
    int nb = (n + 1023) / 1024;

    // one-time host-side setup (identical GPU work every call)
    static cudaStream_t s_side = (cudaStream_t)0;
    static cudaEvent_t  ev_fork = nullptr, ev_join = nullptr,
                        ev_a = nullptr, ev_b = nullptr, ev_g2 = nullptr;
    static int s_init = 0;
    if (!s_init) {
        cudaStream_t st;
        cudaEvent_t e0, e1, e2, e3, e4;
        if (cudaStreamCreateWithFlags(&st, cudaStreamNonBlocking) == cudaSuccess &&
            cudaEventCreateWithFlags(&e0, cudaEventDisableTiming) == cudaSuccess &&
            cudaEventCreateWithFlags(&e1, cudaEventDisableTiming) == cudaSuccess &&
            cudaEventCreateWithFlags(&e2, cudaEventDisableTiming) == cudaSuccess &&
            cudaEventCreateWithFlags(&e3, cudaEventDisableTiming) == cudaSuccess &&
            cudaEventCreateWithFlags(&e4, cudaEventDisableTiming) == cudaSuccess) {
            s_side = st; ev_fork = e0; ev_join = e1; ev_a = e2; ev_b = e3; ev_g2 = e4;
        }
        s_init = 1;
    }
    cudaStream_t sp = s_side;
    bool overlap = (s_side != (cudaStream_t)0);

    if (overlap) {
        cudaEventRecord(ev_fork, 0);
        cudaStreamWaitEvent(s_side, ev_fork, 0);
    }

    // CSR build on side stream (concurrent with gemm1)
    k_deg_zero<<<gn256, 256, 0, sp>>>(n);
    k_deg_count<<<ge256, 256, 0, sp>>>(dstp, e, n);
    k_scan1<<<nb, 1024, 0, sp>>>(n);
    k_scan3<<<nb, 1024, 0, sp>>>(n);
    k_fill<<<ge256, 256, 0, sp>>>(srcp, dstp, e, n);
    if (overlap) cudaEventRecord(ev_join, s_side);

    // half split aligned to 128-row gemm tiles and 8-node agg blocks
    int nh = 25088;                       // 196 * 128
    if (nh > n) nh = n;
    int tiles_A = nh / 128;               // 196
    int tiles_B = (n - nh + 127) / 128;   // 195
    int aggA_blocks = (nh + 7) / 8;
    int aggB_blocks = (n - nh + 7) / 8;
    int agg_blocks  = (n + 7) / 8;

    // layer 1: full gemm1 on main stream (overlapped with CSR build)
    k_gemm<0><<<(n + 127) / 128, 256>>>(x, W1, 0, n);
    if (overlap) cudaStreamWaitEvent(0, ev_join, 0);

    if (overlap) {
        // agg1 first half, then signal; gemm2_A on side stream overlaps agg1_B
        k_agg<<<aggA_blocks, 256>>>(b1, 0, nh);
        cudaEventRecord(ev_a, 0);
        k_agg<<<aggB_blocks, 256>>>(b1, nh, n);
        cudaEventRecord(ev_b, 0);

        cudaStreamWaitEvent(s_side, ev_a, 0);
        k_gemm<1><<<tiles_A, 256, 0, s_side>>>(x, W2, 0, nh);
        cudaStreamWaitEvent(s_side, ev_b, 0);
        if (tiles_B > 0) k_gemm<1><<<tiles_B, 256, 0, s_side>>>(x, W2, nh, n);
        cudaEventRecord(ev_g2, s_side);

        cudaStreamWaitEvent(0, ev_g2, 0);
    } else {
        k_agg<<<agg_blocks, 256>>>(b1, 0, n);
        k_gemm<1><<<(n + 127) / 128, 256>>>(x, W2, 0, n);
    }

    // fused agg2 + classifier head
    k_agg_final<<<agg_blocks, 256>>>(b2, Wc, bc, out, n);
}

// round 13
// speedup vs baseline: 1.0732x; 1.0732x over previous
#include <cuda_runtime.h>
#include <cstdint>

#define NMAX 50000
#define EMAX 1600000
#define HD   128

// ---------------- device scratch (static allocation, no cudaMalloc) ----------
__device__ int   g_deg[NMAX];
__device__ float g_dinv[NMAX];
__device__ int   g_rowptr[NMAX + 1];
__device__ int   g_fill[NMAX];
__device__ int   g_col[EMAX];
__device__ int   g_bsum[64];
__device__ float g_hs[(size_t)NMAX * HD];   // h = A @ W (gather source)
__device__ float g_h [(size_t)NMAX * HD];   // layer-1 output

// ---------------- degree ----------------------------------------------------
__global__ void k_deg_zero(int n) {
    int i = blockIdx.x * blockDim.x + threadIdx.x;
    if (i < n) g_deg[i] = 0;
}
__global__ void k_deg_count(const int* __restrict__ dst, int e, int n) {
    int i = blockIdx.x * blockDim.x + threadIdx.x;
    if (i < e) {
        int d = dst[i];
        if ((unsigned)d < (unsigned)n) atomicAdd(&g_deg[d], 1);
    }
}

// ---------------- parallel exclusive scan of deg ----------------------------
__global__ __launch_bounds__(1024) void k_scan1(int n) {
    __shared__ int ss[1024];
    int tid = threadIdx.x;
    int i = blockIdx.x * 1024 + tid;
    int v = (i < n) ? g_deg[i] : 0;
    if (i < n) g_dinv[i] = rsqrtf((float)(v + 1));
    ss[tid] = v;
    __syncthreads();
#pragma unroll
    for (int off = 1; off < 1024; off <<= 1) {
        int t = (tid >= off) ? ss[tid - off] : 0;
        __syncthreads();
        ss[tid] += t;
        __syncthreads();
    }
    if (i < n) g_rowptr[i] = ss[tid] - v;
    if (tid == 1023) g_bsum[blockIdx.x] = ss[1023];
}
__global__ __launch_bounds__(1024) void k_scan3(int n) {
    __shared__ int off_s;
    if (threadIdx.x == 0) {
        int o = 0;
        for (int j = 0; j < (int)blockIdx.x; j++) o += g_bsum[j];
        off_s = o;
    }
    __syncthreads();
    int i = blockIdx.x * 1024 + threadIdx.x;
    if (i >= n) return;
    int rp = g_rowptr[i] + off_s;
    g_rowptr[i] = rp;
    g_fill[i] = rp;
    if (i == n - 1) g_rowptr[n] = rp + g_deg[i];
}
__global__ void k_fill(const int* __restrict__ src,
                       const int* __restrict__ dst, int e, int n) {
    int i = blockIdx.x * blockDim.x + threadIdx.x;
    if (i >= e) return;
    int d = dst[i];
    int s = src[i];
    if ((unsigned)d >= (unsigned)n || (unsigned)s >= (unsigned)n) return;
    int pos = atomicAdd(&g_fill[d], 1);
    if (pos < EMAX) g_col[pos] = s;
}

// ---------------- GEMM: g_hs = A @ W  (M x 128 @ 128 x 128), exact fp32 -----
// 128x128 block tile, 256 threads, 8x8 register tile, fma.rn.f32x2 (FFMA2).
template <int SRC>
__global__ __launch_bounds__(256) void k_gemm(const float* __restrict__ Ax,
                                              const float* __restrict__ W, int M) {
    const float* __restrict__ A = (SRC == 0) ? Ax : g_h;
    __shared__ float XsT[32][132];   // [k][m], padded
    __shared__ float Ws[32][128];    // [k][n]
    int tid = threadIdx.x;
    int row0 = blockIdx.x * 128;
    int tr = tid >> 4;    // 0..15 -> rows tr*8..tr*8+7
    int tc = tid & 15;    // 0..15 -> cols tc*8..tc*8+7

    unsigned long long acc[8][4];    // [i][j2]: packed pair of adjacent columns
#pragma unroll
    for (int i = 0; i < 8; i++)
#pragma unroll
        for (int j = 0; j < 4; j++) acc[i][j] = 0ULL;

    for (int k0 = 0; k0 < 128; k0 += 32) {
#pragma unroll
        for (int l = 0; l < 4; l++) {
            int f = tid + l * 256;        // 0..1023
            int k4 = f >> 7;              // 0..7 (k-group of 4)
            int m = f & 127;              // row within tile
            int grow = row0 + m;
            float4 v = make_float4(0.f, 0.f, 0.f, 0.f);
            if (grow < M) v = *(const float4*)&A[(size_t)grow * 128 + k0 + (k4 << 2)];
            XsT[(k4 << 2) + 0][m] = v.x;
            XsT[(k4 << 2) + 1][m] = v.y;
            XsT[(k4 << 2) + 2][m] = v.z;
            XsT[(k4 << 2) + 3][m] = v.w;
        }
#pragma unroll
        for (int l = 0; l < 4; l++) {
            int f = tid + l * 256;        // 0..1023
            int r = f >> 5;
            int c = (f & 31) << 2;
            *(float4*)&Ws[r][c] = *(const float4*)&W[(size_t)(k0 + r) * 128 + c];
        }
        __syncthreads();
#pragma unroll
        for (int kk = 0; kk < 32; kk++) {
            float a8[8];
            *(float4*)&a8[0] = *(const float4*)&XsT[kk][tr * 8];
            *(float4*)&a8[4] = *(const float4*)&XsT[kk][tr * 8 + 4];
            ulonglong2 t0 = *(const ulonglong2*)&Ws[kk][tc * 8];
            ulonglong2 t1 = *(const ulonglong2*)&Ws[kk][tc * 8 + 4];
            unsigned long long b4[4] = {t0.x, t0.y, t1.x, t1.y};
#pragma unroll
            for (int i = 0; i < 8; i++) {
                unsigned long long aa;
                unsigned int ai = __float_as_uint(a8[i]);
                asm("mov.b64 %0, {%1, %1};" : "=l"(aa) : "r"(ai));
#pragma unroll
                for (int j = 0; j < 4; j++)
                    asm("fma.rn.f32x2 %0, %1, %2, %3;"
                        : "=l"(acc[i][j])
                        : "l"(aa), "l"(b4[j]), "l"(acc[i][j]));
            }
        }
        __syncthreads();
    }
#pragma unroll
    for (int i = 0; i < 8; i++) {
        int row = row0 + tr * 8 + i;
        if (row < M) {
            *(ulonglong2*)&g_hs[(size_t)row * 128 + tc * 8] =
                make_ulonglong2(acc[i][0], acc[i][1]);
            *(ulonglong2*)&g_hs[(size_t)row * 128 + tc * 8 + 4] =
                make_ulonglong2(acc[i][2], acc[i][3]);
        }
    }
}

// ---------------- aggregation: one warp per node, CSR gather, 8-deep MLP ----
__global__ __launch_bounds__(256) void k_agg(const float* __restrict__ bias, int n) {
    int node = (int)((blockIdx.x * blockDim.x + threadIdx.x) >> 5);
    int lane = threadIdx.x & 31;
    if (node >= n) return;
    const float4* __restrict__ hs4 = (const float4*)g_hs;
    float dn = g_dinv[node];
    float4 hv = hs4[(size_t)node * 32 + lane];
    float4 acc;
    acc.x = __fmul_rn(hv.x, dn);
    acc.y = __fmul_rn(hv.y, dn);
    acc.z = __fmul_rn(hv.z, dn);
    acc.w = __fmul_rn(hv.w, dn);
    int beg = __ldg(&g_rowptr[node]);
    int end = __ldg(&g_rowptr[node + 1]);
    int e = beg;
    for (; e + 8 <= end; e += 8) {
        int   s[8];
        float d[8];
        float4 v[8];
#pragma unroll
        for (int u = 0; u < 8; u++) s[u] = __ldg(&g_col[e + u]);
#pragma unroll
        for (int u = 0; u < 8; u++) d[u] = __ldg(&g_dinv[s[u]]);
#pragma unroll
        for (int u = 0; u < 8; u++) v[u] = __ldg(&hs4[(size_t)s[u] * 32 + lane]);
        float4 p0, p1;
        p0.x = (__fmul_rn(v[0].x, d[0]) + __fmul_rn(v[1].x, d[1])) + (__fmul_rn(v[2].x, d[2]) + __fmul_rn(v[3].x, d[3]));
        p0.y = (__fmul_rn(v[0].y, d[0]) + __fmul_rn(v[1].y, d[1])) + (__fmul_rn(v[2].y, d[2]) + __fmul_rn(v[3].y, d[3]));
        p0.z = (__fmul_rn(v[0].z, d[0]) + __fmul_rn(v[1].z, d[1])) + (__fmul_rn(v[2].z, d[2]) + __fmul_rn(v[3].z, d[3]));
        p0.w = (__fmul_rn(v[0].w, d[0]) + __fmul_rn(v[1].w, d[1])) + (__fmul_rn(v[2].w, d[2]) + __fmul_rn(v[3].w, d[3]));
        p1.x = (__fmul_rn(v[4].x, d[4]) + __fmul_rn(v[5].x, d[5])) + (__fmul_rn(v[6].x, d[6]) + __fmul_rn(v[7].x, d[7]));
        p1.y = (__fmul_rn(v[4].y, d[4]) + __fmul_rn(v[5].y, d[5])) + (__fmul_rn(v[6].y, d[6]) + __fmul_rn(v[7].y, d[7]));
        p1.z = (__fmul_rn(v[4].z, d[4]) + __fmul_rn(v[5].z, d[5])) + (__fmul_rn(v[6].z, d[6]) + __fmul_rn(v[7].z, d[7]));
        p1.w = (__fmul_rn(v[4].w, d[4]) + __fmul_rn(v[5].w, d[5])) + (__fmul_rn(v[6].w, d[6]) + __fmul_rn(v[7].w, d[7]));
        acc.x += p0.x + p1.x;
        acc.y += p0.y + p1.y;
        acc.z += p0.z + p1.z;
        acc.w += p0.w + p1.w;
    }
    for (; e < end; e++) {
        int s = __ldg(&g_col[e]);
        float ds = __ldg(&g_dinv[s]);
        float4 v = __ldg(&hs4[(size_t)s * 32 + lane]);
        acc.x += __fmul_rn(v.x, ds);
        acc.y += __fmul_rn(v.y, ds);
        acc.z += __fmul_rn(v.z, ds);
        acc.w += __fmul_rn(v.w, ds);
    }
    float4 bb = __ldg(&((const float4*)bias)[lane]);
    float4 o;
    o.x = fmaxf(fmaf(dn, acc.x, bb.x), 0.f);
    o.y = fmaxf(fmaf(dn, acc.y, bb.y), 0.f);
    o.z = fmaxf(fmaf(dn, acc.z, bb.z), 0.f);
    o.w = fmaxf(fmaf(dn, acc.w, bb.w), 0.f);
    ((float4*)g_h)[(size_t)node * 32 + lane] = o;
}

// ---------------- fused agg2 + classifier head (R10/R11-validated) ----------
__global__ __launch_bounds__(256) void k_agg_final(const float* __restrict__ bias,
                                                   const float* __restrict__ Wc,
                                                   const float* __restrict__ bc,
                                                   float* __restrict__ Out, int n) {
    __shared__ float Wcs[128 * 16];
    __shared__ float bcs[16];
    int tid = threadIdx.x;
    for (int i = tid; i < 128 * 16; i += 256) Wcs[i] = Wc[i];
    if (tid < 16) bcs[tid] = bc[tid];
    __syncthreads();
    int node = (int)((blockIdx.x * blockDim.x + tid) >> 5);
    int lane = tid & 31;
    if (node >= n) return;
    const float4* __restrict__ hs4 = (const float4*)g_hs;
    float dn = g_dinv[node];
    float4 hv = hs4[(size_t)node * 32 + lane];
    float4 acc;
    acc.x = __fmul_rn(hv.x, dn);
    acc.y = __fmul_rn(hv.y, dn);
    acc.z = __fmul_rn(hv.z, dn);
    acc.w = __fmul_rn(hv.w, dn);
    int beg = __ldg(&g_rowptr[node]);
    int end = __ldg(&g_rowptr[node + 1]);
    int e = beg;
    for (; e + 8 <= end; e += 8) {
        int   s[8];
        float d[8];
        float4 v[8];
#pragma unroll
        for (int u = 0; u < 8; u++) s[u] = __ldg(&g_col[e + u]);
#pragma unroll
        for (int u = 0; u < 8; u++) d[u] = __ldg(&g_dinv[s[u]]);
#pragma unroll
        for (int u = 0; u < 8; u++) v[u] = __ldg(&hs4[(size_t)s[u] * 32 + lane]);
        float4 p0, p1;
        p0.x = (__fmul_rn(v[0].x, d[0]) + __fmul_rn(v[1].x, d[1])) + (__fmul_rn(v[2].x, d[2]) + __fmul_rn(v[3].x, d[3]));
        p0.y = (__fmul_rn(v[0].y, d[0]) + __fmul_rn(v[1].y, d[1])) + (__fmul_rn(v[2].y, d[2]) + __fmul_rn(v[3].y, d[3]));
        p0.z = (__fmul_rn(v[0].z, d[0]) + __fmul_rn(v[1].z, d[1])) + (__fmul_rn(v[2].z, d[2]) + __fmul_rn(v[3].z, d[3]));
        p0.w = (__fmul_rn(v[0].w, d[0]) + __fmul_rn(v[1].w, d[1])) + (__fmul_rn(v[2].w, d[2]) + __fmul_rn(v[3].w, d[3]));
        p1.x = (__fmul_rn(v[4].x, d[4]) + __fmul_rn(v[5].x, d[5])) + (__fmul_rn(v[6].x, d[6]) + __fmul_rn(v[7].x, d[7]));
        p1.y = (__fmul_rn(v[4].y, d[4]) + __fmul_rn(v[5].y, d[5])) + (__fmul_rn(v[6].y, d[6]) + __fmul_rn(v[7].y, d[7]));
        p1.z = (__fmul_rn(v[4].z, d[4]) + __fmul_rn(v[5].z, d[5])) + (__fmul_rn(v[6].z, d[6]) + __fmul_rn(v[7].z, d[7]));
        p1.w = (__fmul_rn(v[4].w, d[4]) + __fmul_rn(v[5].w, d[5])) + (__fmul_rn(v[6].w, d[6]) + __fmul_rn(v[7].w, d[7]));
        acc.x += p0.x + p1.x;
        acc.y += p0.y + p1.y;
        acc.z += p0.z + p1.z;
        acc.w += p0.w + p1.w;
    }
    for (; e < end; e++) {
        int s = __ldg(&g_col[e]);
        float ds = __ldg(&g_dinv[s]);
        float4 v = __ldg(&hs4[(size_t)s * 32 + lane]);
        acc.x += __fmul_rn(v.x, ds);
        acc.y += __fmul_rn(v.y, ds);
        acc.z += __fmul_rn(v.z, ds);
        acc.w += __fmul_rn(v.w, ds);
    }
    float4 bb = __ldg(&((const float4*)bias)[lane]);
    float h2[4];
    h2[0] = fmaxf(fmaf(dn, acc.x, bb.x), 0.f);
    h2[1] = fmaxf(fmaf(dn, acc.y, bb.y), 0.f);
    h2[2] = fmaxf(fmaf(dn, acc.z, bb.z), 0.f);
    h2[3] = fmaxf(fmaf(dn, acc.w, bb.w), 0.f);
    float p[16];
#pragma unroll
    for (int j = 0; j < 16; j++) p[j] = 0.f;
    int kbase = lane * 4;
#pragma unroll
    for (int t = 0; t < 4; t++) {
        float ht = h2[t];
        const float* wr = &Wcs[(kbase + t) * 16];
#pragma unroll
        for (int j4 = 0; j4 < 4; j4++) {
            float4 w = *(const float4*)&wr[j4 * 4];
            p[j4 * 4 + 0] += ht * w.x;
            p[j4 * 4 + 1] += ht * w.y;
            p[j4 * 4 + 2] += ht * w.z;
            p[j4 * 4 + 3] += ht * w.w;
        }
    }
#pragma unroll
    for (int off = 16; off >= 1; off >>= 1)
#pragma unroll
        for (int j = 0; j < 16; j++)
            p[j] += __shfl_xor_sync(0xffffffffu, p[j], off);
    if (lane < 4) {
        float4 ov;
        ov.x = p[lane * 4 + 0] + bcs[lane * 4 + 0];
        ov.y = p[lane * 4 + 1] + bcs[lane * 4 + 1];
        ov.z = p[lane * 4 + 2] + bcs[lane * 4 + 2];
        ov.w = p[lane * 4 + 3] + bcs[lane * 4 + 3];
        *(float4*)&Out[(size_t)node * 16 + lane * 4] = ov;
    }
}

// ---------------- launcher (R8 structure: prep ∥ gemm1 only) -----------------
extern "C" void kernel_launch(void* const* d_in, const int* in_sizes, int n_in,
                              void* d_out, int out_size) {
    const float* x  = (const float*)d_in[0];
    const int*   ei = (const int*)d_in[1];
    const float* W1 = (const float*)d_in[2];
    const float* b1 = (const float*)d_in[3];
    const float* W2 = (const float*)d_in[4];
    const float* b2 = (const float*)d_in[5];
    const float* Wc = (const float*)d_in[6];
    const float* bc = (const float*)d_in[7];
    float* out = (float*)d_out;

    int n = in_sizes[0] / HD;       // 50000
    int e = in_sizes[1] / 2;        // 1600000
    const int* srcp = ei;
    const int* dstp = ei + e;

    int gn256 = (n + 255) / 256;
    int ge256 = (e + 255) / 256;
    int nb = (n + 1023) / 1024;

    // one-time host-side setup (identical GPU work every call)
    static cudaStream_t s_side = (cudaStream_t)0;
    static cudaEvent_t  ev_fork = nullptr, ev_join = nullptr;
    static int s_init = 0;
    if (!s_init) {
        cudaStream_t st;
        cudaEvent_t e0, e1;
        if (cudaStreamCreateWithFlags(&st, cudaStreamNonBlocking) == cudaSuccess &&
            cudaEventCreateWithFlags(&e0, cudaEventDisableTiming) == cudaSuccess &&
            cudaEventCreateWithFlags(&e1, cudaEventDisableTiming) == cudaSuccess) {
            s_side = st; ev_fork = e0; ev_join = e1;
        }
        s_init = 1;
    }
    cudaStream_t sp = s_side;
    bool overlap = (s_side != (cudaStream_t)0);

    if (overlap) {
        cudaEventRecord(ev_fork, 0);
        cudaStreamWaitEvent(s_side, ev_fork, 0);
    }

    // CSR build on side stream (concurrent with gemm1)
    k_deg_zero<<<gn256, 256, 0, sp>>>(n);
    k_deg_count<<<ge256, 256, 0, sp>>>(dstp, e, n);
    k_scan1<<<nb, 1024, 0, sp>>>(n);
    k_scan3<<<nb, 1024, 0, sp>>>(n);
    k_fill<<<ge256, 256, 0, sp>>>(srcp, dstp, e, n);
    if (overlap) cudaEventRecord(ev_join, s_side);

    int gemm_blocks = (n + 127) / 128;
    int agg_blocks  = (n + 7) / 8;

    // layer 1
    k_gemm<0><<<gemm_blocks, 256>>>(x, W1, n);
    if (overlap) cudaStreamWaitEvent(0, ev_join, 0);
    k_agg<<<agg_blocks, 256>>>(b1, n);
    // layer 2
    k_gemm<1><<<gemm_blocks, 256>>>(x, W2, n);
    // fused agg2 + classifier head
    k_agg_final<<<agg_blocks, 256>>>(b2, Wc, bc, out, n);
}